// round 15
// baseline (speedup 1.0000x reference)
#include <cuda_runtime.h>

#define BB   1024
#define AA   64
#define NN   256
#define MM   128
#define HH   64
#define EATT 64
#define ACTD 64
#define KK   8
#define ROWS (BB*AA)
#define WS   92
#define WT   (MM - WS)
#define PGRID 148

__device__ float g_thoughts[ROWS * MM];
__device__ float g_newt[ROWS * MM];
__device__ int   g_gidx[ROWS * KK];
__device__ int   g_isinit[ROWS];
__device__ unsigned g_k4_ctr;

__device__ __forceinline__ unsigned long long fma2(unsigned long long a,
                                                   unsigned long long b,
                                                   unsigned long long c)
{
    unsigned long long d;
    asm("fma.rn.f32x2 %0, %1, %2, %3;" : "=l"(d) : "l"(a), "l"(b), "l"(c));
    return d;
}
__device__ __forceinline__ float lohi(unsigned long long v)
{
    return __uint_as_float((unsigned)(v & 0xffffffffull)) +
           __uint_as_float((unsigned)(v >> 32));
}
__device__ __forceinline__ float ftanh(float x)      // accurate (output path)
{
    float e = __expf(2.0f * x);
    return 1.0f - __fdividef(2.0f, e + 1.0f);
}
__device__ __forceinline__ float tanha(float x)      // HW approx (gate path)
{
    float y;
    asm("tanh.approx.f32 %0, %1;" : "=f"(y) : "f"(x));
    return y;
}
__device__ __forceinline__ float sigma(float x)
{
    return fmaf(tanha(0.5f * x), 0.5f, 0.5f);
}

// ======= kA: actor_1, weights in SMEM, persistent, tile-granular ========
__global__ __launch_bounds__(512) void kA_actor1(
    const float* __restrict__ obs,
    const float* __restrict__ w1, const float* __restrict__ b1,
    const float* __restrict__ lng, const float* __restrict__ lnb,
    const float* __restrict__ w2, const float* __restrict__ b2)
{
    extern __shared__ __align__(16) float dyn[];
    float* w1s    = dyn;                 // 128 x 260
    float* w2s    = dyn + 128 * 260;     // 128 x 132
    float* obs_sm = w2s + 128 * 132;     // 16 x 256
    float* h_sm   = obs_sm + 16 * 256;   // 16 x 128
    __shared__ float redA[16][4];
    __shared__ float redB[16][4];

    int tx = threadIdx.x;
    int o  = tx & 127;
    int rh = tx >> 7;
    int wg = (tx >> 5) & 3;

    if (blockIdx.x == 0 && tx == 0) g_k4_ctr = 0;   // reset k4 work counter

    for (int i = tx; i < 128 * 64; i += 512) {
        int r = i >> 6, c = i & 63;
        ((float4*)(w1s + r * 260))[c] = ((const float4*)(w1 + r * 256))[c];
    }
    for (int i = tx; i < 128 * 32; i += 512) {
        int r = i >> 5, c = i & 31;
        ((float4*)(w2s + r * 132))[c] = ((const float4*)(w2 + r * 128))[c];
    }
    float bb1 = b1[o], bb2 = b2[o], lg = lng[o], lb = lnb[o];
    __syncthreads();

    for (int t = blockIdx.x; t < ROWS / 16; t += PGRID) {
        long rowbase = (long)t * 16;
        {
            const float4* src = (const float4*)(obs + rowbase * NN);
            ((float4*)obs_sm)[tx]       = src[tx];
            ((float4*)obs_sm)[tx + 512] = src[tx + 512];
        }
        __syncthreads();

        unsigned long long acc[8];
        #pragma unroll
        for (int i = 0; i < 8; i++) acc[i] = 0ull;
        {
            const float* wr = w1s + o * 260;
            #pragma unroll 4
            for (int jc = 0; jc < NN; jc += 4) {
                longlong2 w = *(const longlong2*)(wr + jc);
                #pragma unroll
                for (int r = 0; r < 4; r++) {
                    longlong2 x = *(const longlong2*)(obs_sm + (rh * 4 + r) * NN + jc);
                    acc[2 * r]     = fma2(w.x, x.x, acc[2 * r]);
                    acc[2 * r + 1] = fma2(w.y, x.y, acc[2 * r + 1]);
                }
            }
        }
        float hv[4];
        #pragma unroll
        for (int r = 0; r < 4; r++) hv[r] = bb1 + lohi(acc[2 * r]) + lohi(acc[2 * r + 1]);

        #pragma unroll
        for (int r = 0; r < 4; r++) {
            float s = hv[r];
            for (int off = 16; off; off >>= 1) s += __shfl_down_sync(0xffffffffu, s, off);
            if ((tx & 31) == 0) redA[rh * 4 + r][wg] = s;
        }
        __syncthreads();
        float mu[4];
        #pragma unroll
        for (int r = 0; r < 4; r++) {
            int row = rh * 4 + r;
            mu[r] = (redA[row][0] + redA[row][1] + redA[row][2] + redA[row][3]) * (1.0f / MM);
        }
        #pragma unroll
        for (int r = 0; r < 4; r++) {
            float d = hv[r] - mu[r];
            float s2 = d * d;
            for (int off = 16; off; off >>= 1) s2 += __shfl_down_sync(0xffffffffu, s2, off);
            if ((tx & 31) == 0) redB[rh * 4 + r][wg] = s2;
        }
        __syncthreads();
        #pragma unroll
        for (int r = 0; r < 4; r++) {
            int row = rh * 4 + r;
            float var = (redB[row][0] + redB[row][1] + redB[row][2] + redB[row][3]) * (1.0f / MM);
            float v = (hv[r] - mu[r]) * rsqrtf(var + 1e-5f) * lg + lb;
            h_sm[row * MM + o] = fmaxf(v, 0.0f);
        }
        __syncthreads();

        #pragma unroll
        for (int i = 0; i < 8; i++) acc[i] = 0ull;
        {
            const float* wr = w2s + o * 132;
            #pragma unroll 4
            for (int jc = 0; jc < MM; jc += 4) {
                longlong2 w = *(const longlong2*)(wr + jc);
                #pragma unroll
                for (int r = 0; r < 4; r++) {
                    longlong2 x = *(const longlong2*)(h_sm + (rh * 4 + r) * MM + jc);
                    acc[2 * r]     = fma2(w.x, x.x, acc[2 * r]);
                    acc[2 * r + 1] = fma2(w.y, x.y, acc[2 * r + 1]);
                }
            }
        }
        #pragma unroll
        for (int r = 0; r < 4; r++)
            g_thoughts[(rowbase + rh * 4 + r) * MM + o] =
                bb2 + lohi(acc[2 * r]) + lohi(acc[2 * r + 1]);
        __syncthreads();
    }
}

// ======= kB: attention MLP, weights in SMEM, persistent, 32-row tiles ===
__global__ __launch_bounds__(512) void kB_att(
    const float* __restrict__ aw1, const float* __restrict__ ab1,
    const float* __restrict__ aw2, const float* __restrict__ ab2,
    const float* __restrict__ aw3, const float* __restrict__ ab3)
{
    extern __shared__ __align__(16) float dyn[];
    float* aw1s = dyn;               // 64 x 132
    float* aw2s = dyn + 64 * 132;    // 64 x 68
    float* t_sm = aw2s + 64 * 68;    // 32 x 128
    float* a_sm = t_sm + 32 * 128;   // 32 x 64
    __shared__ float redL[32][2];

    int tx = threadIdx.x;
    int u  = tx & 63;
    int rg = tx >> 6;
    int hw = (tx >> 5) & 1;

    for (int i = tx; i < 64 * 32; i += 512) {
        int r = i >> 5, c = i & 31;
        ((float4*)(aw1s + r * 132))[c] = ((const float4*)(aw1 + r * 128))[c];
    }
    for (int i = tx; i < 64 * 16; i += 512) {
        int r = i >> 4, c = i & 15;
        ((float4*)(aw2s + r * 68))[c] = ((const float4*)(aw2 + r * 64))[c];
    }
    float bb1 = ab1[u], bb2 = ab2[u], w3u = aw3[u], bb3 = ab3[0];
    __syncthreads();

    for (int t = blockIdx.x; t < ROWS / 32; t += PGRID) {
        long rowbase = (long)t * 32;
        {
            const float4* src = (const float4*)(g_thoughts + rowbase * MM);
            ((float4*)t_sm)[tx]       = src[tx];
            ((float4*)t_sm)[tx + 512] = src[tx + 512];
        }
        __syncthreads();

        unsigned long long acc[8];
        #pragma unroll
        for (int i = 0; i < 8; i++) acc[i] = 0ull;
        {
            const float* wr = aw1s + u * 132;
            #pragma unroll 4
            for (int jc = 0; jc < MM; jc += 4) {
                longlong2 w = *(const longlong2*)(wr + jc);
                #pragma unroll
                for (int r = 0; r < 4; r++) {
                    longlong2 x = *(const longlong2*)(t_sm + (rg * 4 + r) * MM + jc);
                    acc[2 * r]     = fma2(w.x, x.x, acc[2 * r]);
                    acc[2 * r + 1] = fma2(w.y, x.y, acc[2 * r + 1]);
                }
            }
        }
        #pragma unroll
        for (int r = 0; r < 4; r++)
            a_sm[(rg * 4 + r) * EATT + u] =
                fmaxf(bb1 + lohi(acc[2 * r]) + lohi(acc[2 * r + 1]), 0.0f);
        __syncthreads();

        #pragma unroll
        for (int i = 0; i < 8; i++) acc[i] = 0ull;
        {
            const float* wr = aw2s + u * 68;
            #pragma unroll 4
            for (int jc = 0; jc < EATT; jc += 4) {
                longlong2 w = *(const longlong2*)(wr + jc);
                #pragma unroll
                for (int r = 0; r < 4; r++) {
                    longlong2 x = *(const longlong2*)(a_sm + (rg * 4 + r) * EATT + jc);
                    acc[2 * r]     = fma2(w.x, x.x, acc[2 * r]);
                    acc[2 * r + 1] = fma2(w.y, x.y, acc[2 * r + 1]);
                }
            }
        }
        #pragma unroll
        for (int r = 0; r < 4; r++) {
            float c = fmaxf(bb2 + lohi(acc[2 * r]) + lohi(acc[2 * r + 1]), 0.0f);
            float p = w3u * c;
            for (int off = 16; off; off >>= 1) p += __shfl_down_sync(0xffffffffu, p, off);
            if ((tx & 31) == 0) redL[rg * 4 + r][hw] = p;
        }
        __syncthreads();
        if (u == 0) {
            #pragma unroll
            for (int r = 0; r < 4; r++) {
                int row = rg * 4 + r;
                g_isinit[rowbase + row] =
                    ((redL[row][0] + redL[row][1] + bb3) > 0.0f) ? 1 : 0;
            }
        }
        __syncthreads();
    }
}

// ==== k3: distances + stable top-8, sorted; initiator rows only ========
#define TP 132
__global__ __launch_bounds__(256) void k3_groups()
{
    __shared__ __align__(16) float th[AA][TP];
    __shared__ float sq[AA];
    __shared__ int   init_sm[AA];

    int tx = threadIdx.x;
    int b  = blockIdx.x;
    const float* tg = g_thoughts + (long)b * AA * MM;
    for (int i = tx; i < AA * MM; i += 256) th[i >> 7][i & 127] = tg[i];
    if (tx < AA) init_sm[tx] = g_isinit[(long)b * AA + tx];
    __syncthreads();

    if (tx < AA) {
        float s = 0.0f;
        #pragma unroll 16
        for (int c = 0; c < MM; c++) { float v = th[tx][c]; s += v * v; }
        sq[tx] = s;
    }
    __syncthreads();

    int warp = tx >> 5, lane = tx & 31;
    for (int i = warp; i < AA; i += 8) {
        if (!init_sm[i]) continue;          // gidx never read for non-initiators

        int j0 = lane, j1 = lane + 32;
        float d0 = 0.0f, d1 = 0.0f;
        #pragma unroll 8
        for (int c = 0; c < MM; c += 4) {
            float4 xi = *(const float4*)&th[i][c];
            float4 xa = *(const float4*)&th[j0][c];
            float4 xb = *(const float4*)&th[j1][c];
            d0 += xi.x * xa.x + xi.y * xa.y + xi.z * xa.z + xi.w * xa.w;
            d1 += xi.x * xb.x + xi.y * xb.y + xi.z * xb.z + xi.w * xb.w;
        }
        d0 = sq[i] + sq[j0] - 2.0f * d0;
        d1 = sq[i] + sq[j1] - 2.0f * d1;

        int sel[KK];
        #pragma unroll
        for (int t = 0; t < KK; t++) {
            float md; int mj;
            if (d0 <= d1) { md = d0; mj = j0; } else { md = d1; mj = j1; }
            for (int off = 16; off; off >>= 1) {
                float od = __shfl_down_sync(0xffffffffu, md, off);
                int   oj = __shfl_down_sync(0xffffffffu, mj, off);
                if (od < md || (od == md && oj < mj)) { md = od; mj = oj; }
            }
            mj = __shfl_sync(0xffffffffu, mj, 0);
            sel[t] = mj;
            if (mj == j0) d0 = 3.4e38f;
            if (mj == j1) d1 = 3.4e38f;
        }
        #pragma unroll
        for (int p = 0; p < KK; p++)
            #pragma unroll
            for (int q = 0; q < KK - 1; q++)
                if (sel[q] > sel[q + 1]) { int t2 = sel[q]; sel[q] = sel[q + 1]; sel[q + 1] = t2; }
        if (lane < KK) {
            int v = sel[0];
            #pragma unroll
            for (int q = 1; q < KK; q++) if (lane == q) v = sel[q];
            g_gidx[((long)b * AA + i) * KK + lane] = v;
        }
    }
}

// ===== k4: persistent bi-LSTM, dynamic stealing, vectorized scatter =====
__global__ __launch_bounds__(512, 1) void k4_lstm(
    const float* __restrict__ wih_f, const float* __restrict__ whh_f,
    const float* __restrict__ bih_f, const float* __restrict__ bhh_f,
    const float* __restrict__ wih_b, const float* __restrict__ whh_b,
    const float* __restrict__ bih_b, const float* __restrict__ bhh_b)
{
    extern __shared__ __align__(16) float dyn[];
    float* w_sm = dyn;                 // [2][256][WS]
    float* nt   = dyn + 2 * 256 * WS;  // 32 KB

    __shared__ __align__(16) float z_sm[512];
    __shared__ __align__(16) float h_sm[2 * HH];
    __shared__ __align__(16) float hist[2][KK][HH];
    __shared__ int idx_all[AA * KK];
    __shared__ int init_all[AA];
    __shared__ int cur_b;

    int tx  = threadIdx.x;
    int dir = tx >> 8;
    int g   = tx & 255;
    int b1id = 1 + dir;
    int b2id = 3 + dir;

    float bsum = dir ? (bih_b[g] + bhh_b[g]) : (bih_f[g] + bhh_f[g]);

    unsigned long long wr2[HH / 2];
    {
        const float* w = (dir ? whh_b : whh_f) + g * HH;
        #pragma unroll
        for (int j = 0; j < HH; j += 4) {
            longlong2 t = *(const longlong2*)(w + j);
            wr2[(j >> 1)]     = t.x;
            wr2[(j >> 1) + 1] = t.y;
        }
    }
    unsigned long long wt[WT / 2];
    {
        const float* w = (dir ? wih_b : wih_f) + g * MM + WS;
        #pragma unroll
        for (int t = 0; t < WT / 4; t++) {
            longlong2 v = *(const longlong2*)(w + 4 * t);
            wt[2 * t]     = v.x;
            wt[2 * t + 1] = v.y;
        }
    }
    for (int i = tx; i < 2 * 256 * (WS / 4); i += 512) {
        int d   = i / (256 * (WS / 4));
        int rem = i - d * (256 * (WS / 4));
        int r   = rem / (WS / 4);
        int c   = rem - r * (WS / 4);
        ((float4*)(w_sm + (d * 256 + r) * WS))[c] =
            ((const float4*)((d ? wih_b : wih_f) + r * MM))[c];
    }
    const float* wp = w_sm + (dir * 256 + g) * WS;
    bool is_gate = (g < HH);

    for (;;) {
        if (tx == 0) cur_b = (int)atomicAdd(&g_k4_ctr, 1u);
        __syncthreads();                     // broadcast + protect nt reuse
        int b = cur_b;
        if (b >= BB) break;

        {
            const float4* src = (const float4*)(g_thoughts + (long)b * AA * MM);
            float4* dst = (float4*)nt;
            #pragma unroll
            for (int i = 0; i < 4; i++) dst[tx + i * 512] = src[tx + i * 512];
        }
        idx_all[tx] = g_gidx[(long)b * AA * KK + tx];
        if (tx < AA) init_all[tx] = g_isinit[(long)b * AA + tx];
        __syncthreads();

        for (int a = 0; a < AA; a++) {
            if (!init_all[a]) continue;

            float cst = 0.0f;
            #pragma unroll
            for (int p = 0; p < 2; p++) {
                int q0 = dir ? (7 - 4 * p) : (4 * p);
                int q1 = dir ? (6 - 4 * p) : (4 * p + 1);
                int q2 = dir ? (5 - 4 * p) : (4 * p + 2);
                int q3 = dir ? (4 - 4 * p) : (4 * p + 3);
                int ia = idx_all[a * KK + q0] * MM, ib = idx_all[a * KK + q1] * MM;
                int ic = idx_all[a * KK + q2] * MM, id = idx_all[a * KK + q3] * MM;

                unsigned long long a0 = 0ull, a1 = 0ull, a2 = 0ull, a3 = 0ull;
                #pragma unroll 23
                for (int jc = 0; jc < WS; jc += 4) {
                    longlong2 w  = *(const longlong2*)(wp + jc);
                    longlong2 x0 = *(const longlong2*)(nt + ia + jc);
                    longlong2 x1 = *(const longlong2*)(nt + ib + jc);
                    longlong2 x2 = *(const longlong2*)(nt + ic + jc);
                    longlong2 x3 = *(const longlong2*)(nt + id + jc);
                    a0 = fma2(w.x, x0.x, a0); a0 = fma2(w.y, x0.y, a0);
                    a1 = fma2(w.x, x1.x, a1); a1 = fma2(w.y, x1.y, a1);
                    a2 = fma2(w.x, x2.x, a2); a2 = fma2(w.y, x2.y, a2);
                    a3 = fma2(w.x, x3.x, a3); a3 = fma2(w.y, x3.y, a3);
                }
                #pragma unroll
                for (int t = 0; t < WT / 4; t++) {
                    int jc = WS + 4 * t;
                    longlong2 x0 = *(const longlong2*)(nt + ia + jc);
                    longlong2 x1 = *(const longlong2*)(nt + ib + jc);
                    longlong2 x2 = *(const longlong2*)(nt + ic + jc);
                    longlong2 x3 = *(const longlong2*)(nt + id + jc);
                    a0 = fma2(wt[2 * t], x0.x, a0); a0 = fma2(wt[2 * t + 1], x0.y, a0);
                    a1 = fma2(wt[2 * t], x1.x, a1); a1 = fma2(wt[2 * t + 1], x1.y, a1);
                    a2 = fma2(wt[2 * t], x2.x, a2); a2 = fma2(wt[2 * t + 1], x2.y, a2);
                    a3 = fma2(wt[2 * t], x3.x, a3); a3 = fma2(wt[2 * t + 1], x3.y, a3);
                }
                float z0 = bsum + lohi(a0), z1 = bsum + lohi(a1);
                float z2 = bsum + lohi(a2), z3 = bsum + lohi(a3);

                const float* hp = h_sm + dir * HH;
                #pragma unroll
                for (int ss = 0; ss < 4; ss++) {
                    int s  = 4 * p + ss;
                    int ks = dir ? (7 - s) : s;
                    float zin = (ss == 0) ? z0 : (ss == 1) ? z1 : (ss == 2) ? z2 : z3;
                    float zfull;
                    if (p == 0 && ss == 0) {
                        zfull = zin;                 // h == 0: skip dot
                    } else {
                        unsigned long long r0 = 0ull, r1 = 0ull, r2 = 0ull, r3 = 0ull;
                        #pragma unroll
                        for (int j = 0; j < HH; j += 8) {
                            longlong2 ha = *(const longlong2*)(hp + j);
                            longlong2 hb = *(const longlong2*)(hp + j + 4);
                            r0 = fma2(wr2[(j >> 1)],     ha.x, r0);
                            r1 = fma2(wr2[(j >> 1) + 1], ha.y, r1);
                            r2 = fma2(wr2[(j >> 1) + 2], hb.x, r2);
                            r3 = fma2(wr2[(j >> 1) + 3], hb.y, r3);
                        }
                        zfull = zin + (lohi(r0) + lohi(r1)) + (lohi(r2) + lohi(r3));
                    }
                    z_sm[tx] = zfull;
                    if (is_gate) {
                        asm volatile("bar.sync %0, 256;" :: "r"(b1id) : "memory");
                        int base = dir * 256;
                        float zi = z_sm[base + g];
                        float zf = z_sm[base + 64 + g];
                        float zg = z_sm[base + 128 + g];
                        float zo = z_sm[base + 192 + g];
                        cst = sigma(zf) * cst + sigma(zi) * tanha(zg);
                        float h = sigma(zo) * tanha(cst);
                        h_sm[dir * HH + g] = h;
                        hist[dir][ks][g] = h;
                    } else {
                        asm volatile("bar.arrive %0, 256;" :: "r"(b1id) : "memory");
                    }
                    asm volatile("bar.sync %0, 256;" :: "r"(b2id) : "memory");
                }
            }

            __syncthreads();
            if (tx < 256) {                        // vectorized scatter: 8x32 float4
                int k = tx >> 5, c4 = tx & 31;
                float4 v = (c4 < 16) ? ((const float4*)&hist[0][k][0])[c4]
                                     : ((const float4*)&hist[1][k][0])[c4 - 16];
                ((float4*)(nt + idx_all[a * KK + k] * MM))[c4] = v;
            }
            __syncthreads();
        }

        {
            float4* dst = (float4*)(g_newt + (long)b * AA * MM);
            const float4* src = (const float4*)nt;
            #pragma unroll
            for (int i = 0; i < 4; i++) dst[tx + i * 512] = src[tx + i * 512];
        }
    }
}

// ======= k5: actor_2, weights in SMEM, persistent, tile-granular ========
__global__ __launch_bounds__(512) void k5_actor2(
    const float* __restrict__ w1, const float* __restrict__ b1,
    const float* __restrict__ w2, float* __restrict__ out)
{
    extern __shared__ __align__(16) float dyn[];
    float* w1s  = dyn;                 // 128 x 260
    float* w2s  = dyn + 128 * 260;     // 64 x 132
    float* x_sm = w2s + 64 * 132;      // 16 x 256
    float* e_sm = x_sm + 16 * 256;     // 16 x 128

    int tx = threadIdx.x;
    int o  = tx & 127;
    int rh = tx >> 7;

    for (int i = tx; i < 128 * 64; i += 512) {
        int r = i >> 6, c = i & 63;
        ((float4*)(w1s + r * 260))[c] = ((const float4*)(w1 + r * 256))[c];
    }
    for (int i = tx; i < 64 * 32; i += 512) {
        int r = i >> 5, c = i & 31;
        ((float4*)(w2s + r * 132))[c] = ((const float4*)(w2 + r * 128))[c];
    }
    float bb1 = b1[o];
    __syncthreads();

    for (int t = blockIdx.x; t < ROWS / 16; t += PGRID) {
        long rowbase = (long)t * 16;

        for (int i = tx; i < 16 * 32; i += 512) {
            int r = i >> 5, c4 = i & 31;
            float4 tv = ((const float4*)(g_thoughts + (rowbase + r) * MM))[c4];
            float4 nv = ((const float4*)(g_newt     + (rowbase + r) * MM))[c4];
            tv.x = fmaxf(tv.x, 0.f); tv.y = fmaxf(tv.y, 0.f);
            tv.z = fmaxf(tv.z, 0.f); tv.w = fmaxf(tv.w, 0.f);
            nv.x = fmaxf(nv.x, 0.f); nv.y = fmaxf(nv.y, 0.f);
            nv.z = fmaxf(nv.z, 0.f); nv.w = fmaxf(nv.w, 0.f);
            ((float4*)(x_sm + r * 256))[c4]      = tv;
            ((float4*)(x_sm + r * 256 + MM))[c4] = nv;
        }
        __syncthreads();

        unsigned long long acc[8];
        #pragma unroll
        for (int i = 0; i < 8; i++) acc[i] = 0ull;
        {
            const float* wr = w1s + o * 260;
            #pragma unroll 4
            for (int jc = 0; jc < 2 * MM; jc += 4) {
                longlong2 w = *(const longlong2*)(wr + jc);
                #pragma unroll
                for (int r = 0; r < 4; r++) {
                    longlong2 x = *(const longlong2*)(x_sm + (rh * 4 + r) * 256 + jc);
                    acc[2 * r]     = fma2(w.x, x.x, acc[2 * r]);
                    acc[2 * r + 1] = fma2(w.y, x.y, acc[2 * r + 1]);
                }
            }
        }
        #pragma unroll
        for (int r = 0; r < 4; r++)
            e_sm[(rh * 4 + r) * MM + o] = bb1 + lohi(acc[2 * r]) + lohi(acc[2 * r + 1]);
        __syncthreads();

        int u  = tx & 63;
        int rr = tx >> 6;
        unsigned long long c0a = 0ull, c0b = 0ull, c1a = 0ull, c1b = 0ull;
        {
            const float* wr = w2s + u * 132;
            #pragma unroll 4
            for (int jc = 0; jc < MM; jc += 4) {
                longlong2 w = *(const longlong2*)(wr + jc);
                longlong2 xa = *(const longlong2*)(e_sm + rr * MM + jc);
                longlong2 xb = *(const longlong2*)(e_sm + (rr + 8) * MM + jc);
                c0a = fma2(w.x, xa.x, c0a);  c0b = fma2(w.y, xa.y, c0b);
                c1a = fma2(w.x, xb.x, c1a);  c1b = fma2(w.y, xb.y, c1b);
            }
        }
        out[(rowbase + rr) * ACTD + u]     = ftanh(lohi(c0a) + lohi(c0b));
        out[(rowbase + rr + 8) * ACTD + u] = ftanh(lohi(c1a) + lohi(c1b));
        __syncthreads();
    }
}

// =======================================================================
extern "C" void kernel_launch(void* const* d_in, const int* in_sizes, int n_in,
                              void* d_out, int out_size)
{
    const float* obs    = (const float*)d_in[0];
    const float* a1_w1  = (const float*)d_in[1];
    const float* a1_b1  = (const float*)d_in[2];
    const float* ln_g   = (const float*)d_in[3];
    const float* ln_b   = (const float*)d_in[4];
    const float* a1_w2  = (const float*)d_in[5];
    const float* a1_b2  = (const float*)d_in[6];
    const float* att_w1 = (const float*)d_in[7];
    const float* att_b1 = (const float*)d_in[8];
    const float* att_w2 = (const float*)d_in[9];
    const float* att_b2 = (const float*)d_in[10];
    const float* att_w3 = (const float*)d_in[11];
    const float* att_b3 = (const float*)d_in[12];
    const float* wih_f  = (const float*)d_in[13];
    const float* whh_f  = (const float*)d_in[14];
    const float* bih_f  = (const float*)d_in[15];
    const float* bhh_f  = (const float*)d_in[16];
    const float* wih_b  = (const float*)d_in[17];
    const float* whh_b  = (const float*)d_in[18];
    const float* bih_b  = (const float*)d_in[19];
    const float* bhh_b  = (const float*)d_in[20];
    const float* a2_w1  = (const float*)d_in[21];
    const float* a2_b1  = (const float*)d_in[22];
    const float* a2_w2  = (const float*)d_in[23];
    float* out = (float*)d_out;

    const int kA_smem = (128 * 260 + 128 * 132 + 16 * 256 + 16 * 128) * 4;
    const int kB_smem = (64 * 132 + 64 * 68 + 32 * 128 + 32 * 64) * 4;
    const int k4_smem = (2 * 256 * WS + AA * MM) * 4;
    const int k5_smem = (128 * 260 + 64 * 132 + 16 * 256 + 16 * 128) * 4;
    static int attr_done = 0;
    if (!attr_done) {
        cudaFuncSetAttribute(kA_actor1, cudaFuncAttributeMaxDynamicSharedMemorySize, kA_smem);
        cudaFuncSetAttribute(kB_att,    cudaFuncAttributeMaxDynamicSharedMemorySize, kB_smem);
        cudaFuncSetAttribute(k4_lstm,   cudaFuncAttributeMaxDynamicSharedMemorySize, k4_smem);
        cudaFuncSetAttribute(k5_actor2, cudaFuncAttributeMaxDynamicSharedMemorySize, k5_smem);
        attr_done = 1;
    }

    kA_actor1<<<PGRID, 512, kA_smem>>>(obs, a1_w1, a1_b1, ln_g, ln_b, a1_w2, a1_b2);
    kB_att<<<PGRID, 512, kB_smem>>>(att_w1, att_b1, att_w2, att_b2, att_w3, att_b3);
    k3_groups<<<BB, 256>>>();
    k4_lstm<<<PGRID, 512, k4_smem>>>(wih_f, whh_f, bih_f, bhh_f, wih_b, whh_b, bih_b, bhh_b);
    k5_actor2<<<PGRID, 512, k5_smem>>>(a2_w1, a2_b1, a2_w2, out);
}

// round 16
// speedup vs baseline: 1.0799x; 1.0799x over previous
#include <cuda_runtime.h>

#define BB   1024
#define AA   64
#define NN   256
#define MM   128
#define HH   64
#define EATT 64
#define ACTD 64
#define KK   8
#define ROWS (BB*AA)
#define WS   92
#define WT   (MM - WS)
#define PGRID 148

__device__ float g_thoughts[ROWS * MM];
__device__ float g_newt[ROWS * MM];
__device__ int   g_gidx[ROWS * KK];
__device__ int   g_isinit[ROWS];
__device__ unsigned g_k4_ctr;

__device__ __forceinline__ unsigned long long fma2(unsigned long long a,
                                                   unsigned long long b,
                                                   unsigned long long c)
{
    unsigned long long d;
    asm("fma.rn.f32x2 %0, %1, %2, %3;" : "=l"(d) : "l"(a), "l"(b), "l"(c));
    return d;
}
__device__ __forceinline__ float lohi(unsigned long long v)
{
    return __uint_as_float((unsigned)(v & 0xffffffffull)) +
           __uint_as_float((unsigned)(v >> 32));
}
__device__ __forceinline__ float ftanh(float x)      // accurate (output path)
{
    float e = __expf(2.0f * x);
    return 1.0f - __fdividef(2.0f, e + 1.0f);
}
__device__ __forceinline__ float tanha(float x)      // HW approx (gate path)
{
    float y;
    asm("tanh.approx.f32 %0, %1;" : "=f"(y) : "f"(x));
    return y;
}
__device__ __forceinline__ float sigma(float x)
{
    return fmaf(tanha(0.5f * x), 0.5f, 0.5f);
}

__global__ void k0_reset() { g_k4_ctr = 0; }

// ======= kA: actor_1, weights in SMEM, persistent, tile-granular ========
__global__ __launch_bounds__(512) void kA_actor1(
    const float* __restrict__ obs,
    const float* __restrict__ w1, const float* __restrict__ b1,
    const float* __restrict__ lng, const float* __restrict__ lnb,
    const float* __restrict__ w2, const float* __restrict__ b2)
{
    extern __shared__ __align__(16) float dyn[];
    float* w1s    = dyn;                 // 128 x 260
    float* w2s    = dyn + 128 * 260;     // 128 x 132
    float* obs_sm = w2s + 128 * 132;     // 16 x 256
    float* h_sm   = obs_sm + 16 * 256;   // 16 x 128
    __shared__ float redA[16][4];
    __shared__ float redB[16][4];

    int tx = threadIdx.x;
    int o  = tx & 127;
    int rh = tx >> 7;
    int wg = (tx >> 5) & 3;

    for (int i = tx; i < 128 * 64; i += 512) {
        int r = i >> 6, c = i & 63;
        ((float4*)(w1s + r * 260))[c] = ((const float4*)(w1 + r * 256))[c];
    }
    for (int i = tx; i < 128 * 32; i += 512) {
        int r = i >> 5, c = i & 31;
        ((float4*)(w2s + r * 132))[c] = ((const float4*)(w2 + r * 128))[c];
    }
    float bb1 = b1[o], bb2 = b2[o], lg = lng[o], lb = lnb[o];
    __syncthreads();

    for (int t = blockIdx.x; t < ROWS / 16; t += PGRID) {
        long rowbase = (long)t * 16;
        {
            const float4* src = (const float4*)(obs + rowbase * NN);
            ((float4*)obs_sm)[tx]       = src[tx];
            ((float4*)obs_sm)[tx + 512] = src[tx + 512];
        }
        __syncthreads();

        unsigned long long acc[8];
        #pragma unroll
        for (int i = 0; i < 8; i++) acc[i] = 0ull;
        {
            const float* wr = w1s + o * 260;
            #pragma unroll 4
            for (int jc = 0; jc < NN; jc += 4) {
                longlong2 w = *(const longlong2*)(wr + jc);
                #pragma unroll
                for (int r = 0; r < 4; r++) {
                    longlong2 x = *(const longlong2*)(obs_sm + (rh * 4 + r) * NN + jc);
                    acc[2 * r]     = fma2(w.x, x.x, acc[2 * r]);
                    acc[2 * r + 1] = fma2(w.y, x.y, acc[2 * r + 1]);
                }
            }
        }
        float hv[4];
        #pragma unroll
        for (int r = 0; r < 4; r++) hv[r] = bb1 + lohi(acc[2 * r]) + lohi(acc[2 * r + 1]);

        #pragma unroll
        for (int r = 0; r < 4; r++) {
            float s = hv[r];
            for (int off = 16; off; off >>= 1) s += __shfl_down_sync(0xffffffffu, s, off);
            if ((tx & 31) == 0) redA[rh * 4 + r][wg] = s;
        }
        __syncthreads();
        float mu[4];
        #pragma unroll
        for (int r = 0; r < 4; r++) {
            int row = rh * 4 + r;
            mu[r] = (redA[row][0] + redA[row][1] + redA[row][2] + redA[row][3]) * (1.0f / MM);
        }
        #pragma unroll
        for (int r = 0; r < 4; r++) {
            float d = hv[r] - mu[r];
            float s2 = d * d;
            for (int off = 16; off; off >>= 1) s2 += __shfl_down_sync(0xffffffffu, s2, off);
            if ((tx & 31) == 0) redB[rh * 4 + r][wg] = s2;
        }
        __syncthreads();
        #pragma unroll
        for (int r = 0; r < 4; r++) {
            int row = rh * 4 + r;
            float var = (redB[row][0] + redB[row][1] + redB[row][2] + redB[row][3]) * (1.0f / MM);
            float v = (hv[r] - mu[r]) * rsqrtf(var + 1e-5f) * lg + lb;
            h_sm[row * MM + o] = fmaxf(v, 0.0f);
        }
        __syncthreads();

        #pragma unroll
        for (int i = 0; i < 8; i++) acc[i] = 0ull;
        {
            const float* wr = w2s + o * 132;
            #pragma unroll 4
            for (int jc = 0; jc < MM; jc += 4) {
                longlong2 w = *(const longlong2*)(wr + jc);
                #pragma unroll
                for (int r = 0; r < 4; r++) {
                    longlong2 x = *(const longlong2*)(h_sm + (rh * 4 + r) * MM + jc);
                    acc[2 * r]     = fma2(w.x, x.x, acc[2 * r]);
                    acc[2 * r + 1] = fma2(w.y, x.y, acc[2 * r + 1]);
                }
            }
        }
        #pragma unroll
        for (int r = 0; r < 4; r++)
            g_thoughts[(rowbase + rh * 4 + r) * MM + o] =
                bb2 + lohi(acc[2 * r]) + lohi(acc[2 * r + 1]);
        __syncthreads();
    }
}

// ======= kB: attention MLP, weights in SMEM, persistent, 32-row tiles ===
__global__ __launch_bounds__(512) void kB_att(
    const float* __restrict__ aw1, const float* __restrict__ ab1,
    const float* __restrict__ aw2, const float* __restrict__ ab2,
    const float* __restrict__ aw3, const float* __restrict__ ab3)
{
    extern __shared__ __align__(16) float dyn[];
    float* aw1s = dyn;               // 64 x 132
    float* aw2s = dyn + 64 * 132;    // 64 x 68
    float* t_sm = aw2s + 64 * 68;    // 32 x 128
    float* a_sm = t_sm + 32 * 128;   // 32 x 64
    __shared__ float redL[32][2];

    int tx = threadIdx.x;
    int u  = tx & 63;
    int rg = tx >> 6;
    int hw = (tx >> 5) & 1;

    for (int i = tx; i < 64 * 32; i += 512) {
        int r = i >> 5, c = i & 31;
        ((float4*)(aw1s + r * 132))[c] = ((const float4*)(aw1 + r * 128))[c];
    }
    for (int i = tx; i < 64 * 16; i += 512) {
        int r = i >> 4, c = i & 15;
        ((float4*)(aw2s + r * 68))[c] = ((const float4*)(aw2 + r * 64))[c];
    }
    float bb1 = ab1[u], bb2 = ab2[u], w3u = aw3[u], bb3 = ab3[0];
    __syncthreads();

    for (int t = blockIdx.x; t < ROWS / 32; t += PGRID) {
        long rowbase = (long)t * 32;
        {
            const float4* src = (const float4*)(g_thoughts + rowbase * MM);
            ((float4*)t_sm)[tx]       = src[tx];
            ((float4*)t_sm)[tx + 512] = src[tx + 512];
        }
        __syncthreads();

        unsigned long long acc[8];
        #pragma unroll
        for (int i = 0; i < 8; i++) acc[i] = 0ull;
        {
            const float* wr = aw1s + u * 132;
            #pragma unroll 4
            for (int jc = 0; jc < MM; jc += 4) {
                longlong2 w = *(const longlong2*)(wr + jc);
                #pragma unroll
                for (int r = 0; r < 4; r++) {
                    longlong2 x = *(const longlong2*)(t_sm + (rg * 4 + r) * MM + jc);
                    acc[2 * r]     = fma2(w.x, x.x, acc[2 * r]);
                    acc[2 * r + 1] = fma2(w.y, x.y, acc[2 * r + 1]);
                }
            }
        }
        #pragma unroll
        for (int r = 0; r < 4; r++)
            a_sm[(rg * 4 + r) * EATT + u] =
                fmaxf(bb1 + lohi(acc[2 * r]) + lohi(acc[2 * r + 1]), 0.0f);
        __syncthreads();

        #pragma unroll
        for (int i = 0; i < 8; i++) acc[i] = 0ull;
        {
            const float* wr = aw2s + u * 68;
            #pragma unroll 4
            for (int jc = 0; jc < EATT; jc += 4) {
                longlong2 w = *(const longlong2*)(wr + jc);
                #pragma unroll
                for (int r = 0; r < 4; r++) {
                    longlong2 x = *(const longlong2*)(a_sm + (rg * 4 + r) * EATT + jc);
                    acc[2 * r]     = fma2(w.x, x.x, acc[2 * r]);
                    acc[2 * r + 1] = fma2(w.y, x.y, acc[2 * r + 1]);
                }
            }
        }
        #pragma unroll
        for (int r = 0; r < 4; r++) {
            float c = fmaxf(bb2 + lohi(acc[2 * r]) + lohi(acc[2 * r + 1]), 0.0f);
            float p = w3u * c;
            for (int off = 16; off; off >>= 1) p += __shfl_down_sync(0xffffffffu, p, off);
            if ((tx & 31) == 0) redL[rg * 4 + r][hw] = p;
        }
        __syncthreads();
        if (u == 0) {
            #pragma unroll
            for (int r = 0; r < 4; r++) {
                int row = rg * 4 + r;
                g_isinit[rowbase + row] =
                    ((redL[row][0] + redL[row][1] + bb3) > 0.0f) ? 1 : 0;
            }
        }
        __syncthreads();
    }
}

// ==== k3: distances + stable top-8, sorted; initiator rows only ========
#define TP 132
__global__ __launch_bounds__(256) void k3_groups()
{
    __shared__ __align__(16) float th[AA][TP];
    __shared__ float sq[AA];
    __shared__ int   init_sm[AA];

    int tx = threadIdx.x;
    int b  = blockIdx.x;
    const float* tg = g_thoughts + (long)b * AA * MM;
    for (int i = tx; i < AA * MM; i += 256) th[i >> 7][i & 127] = tg[i];
    if (tx < AA) init_sm[tx] = g_isinit[(long)b * AA + tx];
    __syncthreads();

    if (tx < AA) {
        float s = 0.0f;
        #pragma unroll 16
        for (int c = 0; c < MM; c++) { float v = th[tx][c]; s += v * v; }
        sq[tx] = s;
    }
    __syncthreads();

    int warp = tx >> 5, lane = tx & 31;
    for (int i = warp; i < AA; i += 8) {
        if (!init_sm[i]) continue;          // gidx never read for non-initiators

        int j0 = lane, j1 = lane + 32;
        float d0 = 0.0f, d1 = 0.0f;
        #pragma unroll 8
        for (int c = 0; c < MM; c += 4) {
            float4 xi = *(const float4*)&th[i][c];
            float4 xa = *(const float4*)&th[j0][c];
            float4 xb = *(const float4*)&th[j1][c];
            d0 += xi.x * xa.x + xi.y * xa.y + xi.z * xa.z + xi.w * xa.w;
            d1 += xi.x * xb.x + xi.y * xb.y + xi.z * xb.z + xi.w * xb.w;
        }
        d0 = sq[i] + sq[j0] - 2.0f * d0;
        d1 = sq[i] + sq[j1] - 2.0f * d1;

        int sel[KK];
        #pragma unroll
        for (int t = 0; t < KK; t++) {
            float md; int mj;
            if (d0 <= d1) { md = d0; mj = j0; } else { md = d1; mj = j1; }
            for (int off = 16; off; off >>= 1) {
                float od = __shfl_down_sync(0xffffffffu, md, off);
                int   oj = __shfl_down_sync(0xffffffffu, mj, off);
                if (od < md || (od == md && oj < mj)) { md = od; mj = oj; }
            }
            mj = __shfl_sync(0xffffffffu, mj, 0);
            sel[t] = mj;
            if (mj == j0) d0 = 3.4e38f;
            if (mj == j1) d1 = 3.4e38f;
        }
        #pragma unroll
        for (int p = 0; p < KK; p++)
            #pragma unroll
            for (int q = 0; q < KK - 1; q++)
                if (sel[q] > sel[q + 1]) { int t2 = sel[q]; sel[q] = sel[q + 1]; sel[q + 1] = t2; }
        if (lane < KK) {
            int v = sel[0];
            #pragma unroll
            for (int q = 1; q < KK; q++) if (lane == q) v = sel[q];
            g_gidx[((long)b * AA + i) * KK + lane] = v;
        }
    }
}

// ===== k4: persistent bi-LSTM, dynamic batch stealing (R13 body) ========
__global__ __launch_bounds__(512, 1) void k4_lstm(
    const float* __restrict__ wih_f, const float* __restrict__ whh_f,
    const float* __restrict__ bih_f, const float* __restrict__ bhh_f,
    const float* __restrict__ wih_b, const float* __restrict__ whh_b,
    const float* __restrict__ bih_b, const float* __restrict__ bhh_b)
{
    extern __shared__ __align__(16) float dyn[];
    float* w_sm = dyn;                 // [2][256][WS]
    float* nt   = dyn + 2 * 256 * WS;  // 32 KB

    __shared__ __align__(16) float z_sm[512];
    __shared__ __align__(16) float h_sm[2 * HH];
    __shared__ __align__(16) float hist[2][KK][HH];
    __shared__ int idx_all[AA * KK];
    __shared__ int init_all[AA];
    __shared__ int cur_b;

    int tx  = threadIdx.x;
    int dir = tx >> 8;
    int g   = tx & 255;
    int b1id = 1 + dir;
    int b2id = 3 + dir;

    float bsum = dir ? (bih_b[g] + bhh_b[g]) : (bih_f[g] + bhh_f[g]);

    unsigned long long wr2[HH / 2];
    {
        const float* w = (dir ? whh_b : whh_f) + g * HH;
        #pragma unroll
        for (int j = 0; j < HH; j += 4) {
            longlong2 t = *(const longlong2*)(w + j);
            wr2[(j >> 1)]     = t.x;
            wr2[(j >> 1) + 1] = t.y;
        }
    }
    unsigned long long wt[WT / 2];
    {
        const float* w = (dir ? wih_b : wih_f) + g * MM + WS;
        #pragma unroll
        for (int t = 0; t < WT / 4; t++) {
            longlong2 v = *(const longlong2*)(w + 4 * t);
            wt[2 * t]     = v.x;
            wt[2 * t + 1] = v.y;
        }
    }
    for (int i = tx; i < 2 * 256 * (WS / 4); i += 512) {
        int d   = i / (256 * (WS / 4));
        int rem = i - d * (256 * (WS / 4));
        int r   = rem / (WS / 4);
        int c   = rem - r * (WS / 4);
        ((float4*)(w_sm + (d * 256 + r) * WS))[c] =
            ((const float4*)((d ? wih_b : wih_f) + r * MM))[c];
    }
    const float* wp = w_sm + (dir * 256 + g) * WS;
    bool is_gate = (g < HH);

    for (;;) {
        if (tx == 0) cur_b = (int)atomicAdd(&g_k4_ctr, 1u);
        __syncthreads();                     // broadcast + protect nt reuse
        int b = cur_b;
        if (b >= BB) break;

        {
            const float4* src = (const float4*)(g_thoughts + (long)b * AA * MM);
            float4* dst = (float4*)nt;
            #pragma unroll
            for (int i = 0; i < 4; i++) dst[tx + i * 512] = src[tx + i * 512];
        }
        idx_all[tx] = g_gidx[(long)b * AA * KK + tx];
        if (tx < AA) init_all[tx] = g_isinit[(long)b * AA + tx];
        __syncthreads();

        for (int a = 0; a < AA; a++) {
            if (!init_all[a]) continue;

            float cst = 0.0f;
            #pragma unroll
            for (int p = 0; p < 2; p++) {
                int q0 = dir ? (7 - 4 * p) : (4 * p);
                int q1 = dir ? (6 - 4 * p) : (4 * p + 1);
                int q2 = dir ? (5 - 4 * p) : (4 * p + 2);
                int q3 = dir ? (4 - 4 * p) : (4 * p + 3);
                int ia = idx_all[a * KK + q0] * MM, ib = idx_all[a * KK + q1] * MM;
                int ic = idx_all[a * KK + q2] * MM, id = idx_all[a * KK + q3] * MM;

                unsigned long long a0 = 0ull, a1 = 0ull, a2 = 0ull, a3 = 0ull;
                #pragma unroll 23
                for (int jc = 0; jc < WS; jc += 4) {
                    longlong2 w  = *(const longlong2*)(wp + jc);
                    longlong2 x0 = *(const longlong2*)(nt + ia + jc);
                    longlong2 x1 = *(const longlong2*)(nt + ib + jc);
                    longlong2 x2 = *(const longlong2*)(nt + ic + jc);
                    longlong2 x3 = *(const longlong2*)(nt + id + jc);
                    a0 = fma2(w.x, x0.x, a0); a0 = fma2(w.y, x0.y, a0);
                    a1 = fma2(w.x, x1.x, a1); a1 = fma2(w.y, x1.y, a1);
                    a2 = fma2(w.x, x2.x, a2); a2 = fma2(w.y, x2.y, a2);
                    a3 = fma2(w.x, x3.x, a3); a3 = fma2(w.y, x3.y, a3);
                }
                #pragma unroll
                for (int t = 0; t < WT / 4; t++) {
                    int jc = WS + 4 * t;
                    longlong2 x0 = *(const longlong2*)(nt + ia + jc);
                    longlong2 x1 = *(const longlong2*)(nt + ib + jc);
                    longlong2 x2 = *(const longlong2*)(nt + ic + jc);
                    longlong2 x3 = *(const longlong2*)(nt + id + jc);
                    a0 = fma2(wt[2 * t], x0.x, a0); a0 = fma2(wt[2 * t + 1], x0.y, a0);
                    a1 = fma2(wt[2 * t], x1.x, a1); a1 = fma2(wt[2 * t + 1], x1.y, a1);
                    a2 = fma2(wt[2 * t], x2.x, a2); a2 = fma2(wt[2 * t + 1], x2.y, a2);
                    a3 = fma2(wt[2 * t], x3.x, a3); a3 = fma2(wt[2 * t + 1], x3.y, a3);
                }
                float z0 = bsum + lohi(a0), z1 = bsum + lohi(a1);
                float z2 = bsum + lohi(a2), z3 = bsum + lohi(a3);

                const float* hp = h_sm + dir * HH;
                #pragma unroll
                for (int ss = 0; ss < 4; ss++) {
                    int s  = 4 * p + ss;
                    int ks = dir ? (7 - s) : s;
                    float zin = (ss == 0) ? z0 : (ss == 1) ? z1 : (ss == 2) ? z2 : z3;
                    float zfull;
                    if (p == 0 && ss == 0) {
                        zfull = zin;                 // h == 0: skip dot
                    } else {
                        unsigned long long r0 = 0ull, r1 = 0ull, r2 = 0ull, r3 = 0ull;
                        #pragma unroll
                        for (int j = 0; j < HH; j += 8) {
                            longlong2 ha = *(const longlong2*)(hp + j);
                            longlong2 hb = *(const longlong2*)(hp + j + 4);
                            r0 = fma2(wr2[(j >> 1)],     ha.x, r0);
                            r1 = fma2(wr2[(j >> 1) + 1], ha.y, r1);
                            r2 = fma2(wr2[(j >> 1) + 2], hb.x, r2);
                            r3 = fma2(wr2[(j >> 1) + 3], hb.y, r3);
                        }
                        zfull = zin + (lohi(r0) + lohi(r1)) + (lohi(r2) + lohi(r3));
                    }
                    z_sm[tx] = zfull;
                    if (is_gate) {
                        asm volatile("bar.sync %0, 256;" :: "r"(b1id) : "memory");
                        int base = dir * 256;
                        float zi = z_sm[base + g];
                        float zf = z_sm[base + 64 + g];
                        float zg = z_sm[base + 128 + g];
                        float zo = z_sm[base + 192 + g];
                        cst = sigma(zf) * cst + sigma(zi) * tanha(zg);
                        float h = sigma(zo) * tanha(cst);
                        h_sm[dir * HH + g] = h;
                        hist[dir][ks][g] = h;
                    } else {
                        asm volatile("bar.arrive %0, 256;" :: "r"(b1id) : "memory");
                    }
                    asm volatile("bar.sync %0, 256;" :: "r"(b2id) : "memory");
                }
            }

            __syncthreads();
            for (int e = tx; e < KK * MM; e += 512) {
                int k = e >> 7, c = e & 127;
                float v = (c < HH) ? hist[0][k][c] : hist[1][k][c - HH];
                nt[idx_all[a * KK + k] * MM + c] = v;
            }
            __syncthreads();
        }

        {
            float4* dst = (float4*)(g_newt + (long)b * AA * MM);
            const float4* src = (const float4*)nt;
            #pragma unroll
            for (int i = 0; i < 4; i++) dst[tx + i * 512] = src[tx + i * 512];
        }
    }
}

// ======= k5: actor_2, weights in SMEM, persistent, tile-granular ========
__global__ __launch_bounds__(512) void k5_actor2(
    const float* __restrict__ w1, const float* __restrict__ b1,
    const float* __restrict__ w2, float* __restrict__ out)
{
    extern __shared__ __align__(16) float dyn[];
    float* w1s  = dyn;                 // 128 x 260
    float* w2s  = dyn + 128 * 260;     // 64 x 132
    float* x_sm = w2s + 64 * 132;      // 16 x 256
    float* e_sm = x_sm + 16 * 256;     // 16 x 128

    int tx = threadIdx.x;
    int o  = tx & 127;
    int rh = tx >> 7;

    for (int i = tx; i < 128 * 64; i += 512) {
        int r = i >> 6, c = i & 63;
        ((float4*)(w1s + r * 260))[c] = ((const float4*)(w1 + r * 256))[c];
    }
    for (int i = tx; i < 64 * 32; i += 512) {
        int r = i >> 5, c = i & 31;
        ((float4*)(w2s + r * 132))[c] = ((const float4*)(w2 + r * 128))[c];
    }
    float bb1 = b1[o];
    __syncthreads();

    for (int t = blockIdx.x; t < ROWS / 16; t += PGRID) {
        long rowbase = (long)t * 16;

        for (int i = tx; i < 16 * 32; i += 512) {
            int r = i >> 5, c4 = i & 31;
            float4 tv = ((const float4*)(g_thoughts + (rowbase + r) * MM))[c4];
            float4 nv = ((const float4*)(g_newt     + (rowbase + r) * MM))[c4];
            tv.x = fmaxf(tv.x, 0.f); tv.y = fmaxf(tv.y, 0.f);
            tv.z = fmaxf(tv.z, 0.f); tv.w = fmaxf(tv.w, 0.f);
            nv.x = fmaxf(nv.x, 0.f); nv.y = fmaxf(nv.y, 0.f);
            nv.z = fmaxf(nv.z, 0.f); nv.w = fmaxf(nv.w, 0.f);
            ((float4*)(x_sm + r * 256))[c4]      = tv;
            ((float4*)(x_sm + r * 256 + MM))[c4] = nv;
        }
        __syncthreads();

        unsigned long long acc[8];
        #pragma unroll
        for (int i = 0; i < 8; i++) acc[i] = 0ull;
        {
            const float* wr = w1s + o * 260;
            #pragma unroll 4
            for (int jc = 0; jc < 2 * MM; jc += 4) {
                longlong2 w = *(const longlong2*)(wr + jc);
                #pragma unroll
                for (int r = 0; r < 4; r++) {
                    longlong2 x = *(const longlong2*)(x_sm + (rh * 4 + r) * 256 + jc);
                    acc[2 * r]     = fma2(w.x, x.x, acc[2 * r]);
                    acc[2 * r + 1] = fma2(w.y, x.y, acc[2 * r + 1]);
                }
            }
        }
        #pragma unroll
        for (int r = 0; r < 4; r++)
            e_sm[(rh * 4 + r) * MM + o] = bb1 + lohi(acc[2 * r]) + lohi(acc[2 * r + 1]);
        __syncthreads();

        int u  = tx & 63;
        int rr = tx >> 6;
        unsigned long long c0a = 0ull, c0b = 0ull, c1a = 0ull, c1b = 0ull;
        {
            const float* wr = w2s + u * 132;
            #pragma unroll 4
            for (int jc = 0; jc < MM; jc += 4) {
                longlong2 w = *(const longlong2*)(wr + jc);
                longlong2 xa = *(const longlong2*)(e_sm + rr * MM + jc);
                longlong2 xb = *(const longlong2*)(e_sm + (rr + 8) * MM + jc);
                c0a = fma2(w.x, xa.x, c0a);  c0b = fma2(w.y, xa.y, c0b);
                c1a = fma2(w.x, xb.x, c1a);  c1b = fma2(w.y, xb.y, c1b);
            }
        }
        out[(rowbase + rr) * ACTD + u]     = ftanh(lohi(c0a) + lohi(c0b));
        out[(rowbase + rr + 8) * ACTD + u] = ftanh(lohi(c1a) + lohi(c1b));
        __syncthreads();
    }
}

// =======================================================================
extern "C" void kernel_launch(void* const* d_in, const int* in_sizes, int n_in,
                              void* d_out, int out_size)
{
    const float* obs    = (const float*)d_in[0];
    const float* a1_w1  = (const float*)d_in[1];
    const float* a1_b1  = (const float*)d_in[2];
    const float* ln_g   = (const float*)d_in[3];
    const float* ln_b   = (const float*)d_in[4];
    const float* a1_w2  = (const float*)d_in[5];
    const float* a1_b2  = (const float*)d_in[6];
    const float* att_w1 = (const float*)d_in[7];
    const float* att_b1 = (const float*)d_in[8];
    const float* att_w2 = (const float*)d_in[9];
    const float* att_b2 = (const float*)d_in[10];
    const float* att_w3 = (const float*)d_in[11];
    const float* att_b3 = (const float*)d_in[12];
    const float* wih_f  = (const float*)d_in[13];
    const float* whh_f  = (const float*)d_in[14];
    const float* bih_f  = (const float*)d_in[15];
    const float* bhh_f  = (const float*)d_in[16];
    const float* wih_b  = (const float*)d_in[17];
    const float* whh_b  = (const float*)d_in[18];
    const float* bih_b  = (const float*)d_in[19];
    const float* bhh_b  = (const float*)d_in[20];
    const float* a2_w1  = (const float*)d_in[21];
    const float* a2_b1  = (const float*)d_in[22];
    const float* a2_w2  = (const float*)d_in[23];
    float* out = (float*)d_out;

    const int kA_smem = (128 * 260 + 128 * 132 + 16 * 256 + 16 * 128) * 4;
    const int kB_smem = (64 * 132 + 64 * 68 + 32 * 128 + 32 * 64) * 4;
    const int k4_smem = (2 * 256 * WS + AA * MM) * 4;
    const int k5_smem = (128 * 260 + 64 * 132 + 16 * 256 + 16 * 128) * 4;
    static int attr_done = 0;
    if (!attr_done) {
        cudaFuncSetAttribute(kA_actor1, cudaFuncAttributeMaxDynamicSharedMemorySize, kA_smem);
        cudaFuncSetAttribute(kB_att,    cudaFuncAttributeMaxDynamicSharedMemorySize, kB_smem);
        cudaFuncSetAttribute(k4_lstm,   cudaFuncAttributeMaxDynamicSharedMemorySize, k4_smem);
        cudaFuncSetAttribute(k5_actor2, cudaFuncAttributeMaxDynamicSharedMemorySize, k5_smem);
        attr_done = 1;
    }

    k0_reset<<<1, 1>>>();
    kA_actor1<<<PGRID, 512, kA_smem>>>(obs, a1_w1, a1_b1, ln_g, ln_b, a1_w2, a1_b2);
    kB_att<<<PGRID, 512, kB_smem>>>(att_w1, att_b1, att_w2, att_b2, att_w3, att_b3);
    k3_groups<<<BB, 256>>>();
    k4_lstm<<<PGRID, 512, k4_smem>>>(wih_f, whh_f, bih_f, bhh_f, wih_b, whh_b, bih_b, bhh_b);
    k5_actor2<<<PGRID, 512, k5_smem>>>(a2_w1, a2_b1, a2_w2, out);
}